// round 14
// baseline (speedup 1.0000x reference)
#include <cuda_runtime.h>
#include <math.h>
#include <stdint.h>

#define HIDDEN   2048
#define HEADS    16
#define HEAD_DIM 128
#define BATCH    2
#define SEQ      1024
#define MROWS    (BATCH*SEQ)

// ---------------- scratch (allocation-free: device globals) ----------------
__device__ float g_q[BATCH*HEADS*SEQ*HEAD_DIM];
__device__ float g_k[BATCH*HEADS*SEQ*HEAD_DIM];
__device__ float g_v[BATCH*HEADS*SEQ*HEAD_DIM];
__device__ float g_attn[MROWS*HIDDEN];
__device__ float g_xc[MROWS*HIDDEN];        // tf32-rounded x
__device__ float g_wt[4*HIDDEN*HIDDEN];     // tf32-rounded transposed weights [N,K]

// ============================================================================
// helpers
// ============================================================================
__device__ __forceinline__ uint32_t smem_u32(const void* p) {
    uint32_t a;
    asm("{ .reg .u64 t; cvta.to.shared.u64 t, %1; cvt.u32.u64 %0, t; }"
        : "=r"(a) : "l"(p));
    return a;
}
__device__ __forceinline__ float to_tf32(float x) {
    uint32_t u;
    asm("cvt.rna.tf32.f32 %0, %1;" : "=r"(u) : "f"(x));
    return __uint_as_float(u);
}
__device__ __forceinline__ void cpa16(uint32_t s, const void* g) {
    asm volatile("cp.async.cg.shared.global [%0], [%1], 16;" :: "r"(s), "l"(g));
}
#define CPA_COMMIT() asm volatile("cp.async.commit_group;" ::: "memory")
template<int N> __device__ __forceinline__ void cpa_wait() {
    asm volatile("cp.async.wait_group %0;" :: "n"(N) : "memory");
}
__device__ __forceinline__ void mma16n8k8(float* c, const uint32_t* a, const uint32_t* b) {
    asm volatile(
        "mma.sync.aligned.m16n8k8.row.col.f32.tf32.tf32.f32 "
        "{%0,%1,%2,%3}, {%4,%5,%6,%7}, {%8,%9}, {%0,%1,%2,%3};"
        : "+f"(c[0]), "+f"(c[1]), "+f"(c[2]), "+f"(c[3])
        : "r"(a[0]), "r"(a[1]), "r"(a[2]), "r"(a[3]), "r"(b[0]), "r"(b[1]));
}

// 2^x via FMA-pipe polynomial (no MUFU)
__device__ __forceinline__ float exp2c(float x) {
    x = fmaxf(x, -126.f);
    float fl = floorf(x);
    float f  = x - fl;
    int   i  = (int)fl;
    float r = 1.52527338e-5f;
    r = fmaf(r, f, 1.54035304e-4f);
    r = fmaf(r, f, 1.33335581e-3f);
    r = fmaf(r, f, 9.61812911e-3f);
    r = fmaf(r, f, 5.55041087e-2f);
    r = fmaf(r, f, 2.40226507e-1f);
    r = fmaf(r, f, 6.93147181e-1f);
    r = fmaf(r, f, 1.0f);
    return r * __int_as_float((i + 127) << 23);
}
// log2(1+u) for u in [0, ~0.101]
__device__ __forceinline__ float log2p_small(float u) {
    float r = 0.14285714f;
    r = fmaf(r, u, -0.16666667f);
    r = fmaf(r, u, 0.2f);
    r = fmaf(r, u, -0.25f);
    r = fmaf(r, u, 0.33333333f);
    r = fmaf(r, u, -0.5f);
    r = fmaf(r, u, 1.0f);
    return r * u * 1.4426950408889634f;
}

// ============================================================================
// K0a: weight transpose + tf32 round: W[K,N] -> Wt[N,K], 4 matrices (z-grid)
// ============================================================================
__global__ void transpose2048(const float* __restrict__ s0, const float* __restrict__ s1,
                              const float* __restrict__ s2, const float* __restrict__ s3,
                              float* __restrict__ dst)
{
    __shared__ float tile[32][33];
    int z = blockIdx.z;
    const float* src = (z == 0) ? s0 : (z == 1) ? s1 : (z == 2) ? s2 : s3;
    float* d = dst + (size_t)z * HIDDEN * HIDDEN;
    int tx = threadIdx.x & 31, ty = threadIdx.x >> 5;
    int x  = blockIdx.x * 32 + tx, y0 = blockIdx.y * 32 + ty;
#pragma unroll
    for (int j = 0; j < 4; ++j)
        tile[ty + j * 8][tx] = to_tf32(src[(size_t)(y0 + j * 8) * HIDDEN + x]);
    __syncthreads();
    int x2 = blockIdx.y * 32 + tx, y2 = blockIdx.x * 32 + ty;
#pragma unroll
    for (int j = 0; j < 4; ++j)
        d[(size_t)(y2 + j * 8) * HIDDEN + x2] = tile[tx][ty + j * 8];
}

// ============================================================================
// K0b: elementwise tf32 rounding (x only)
// ============================================================================
__global__ void cvt_tf32_kernel(const float* __restrict__ src, float* __restrict__ dst, int n4)
{
    int i = blockIdx.x * blockDim.x + threadIdx.x;
    if (i >= n4) return;
    float4 v = ((const float4*)src)[i];
    v.x = to_tf32(v.x); v.y = to_tf32(v.y); v.z = to_tf32(v.z); v.w = to_tf32(v.w);
    ((float4*)dst)[i] = v;
}

// ============================================================================
// K1/K4: tf32 mma.sync GEMM. C = A[M,K] * Wt[N,K]^T (+bias)
// CTA 128x128, BK=32, 4 warps (64x64), 2-stage cp.async (race-safe order).
// LDS.128 fragment loads via DOUBLE-PAIR k-slice permutation:
//   group g (g=0,1 within a k16 pair): slice tig <-> k=4tig+2g, tig+4 <-> 4tig+2g+1
// One ld.shared.v4 feeds BOTH k8 mma groups. PADK=48 (==16 mod 32) is
// conflict-free for v4 loads (quarter-warp starting banks {0,4,...,28}).
// ============================================================================
#define BM 128
#define BN 128
#define BK 32
#define PADK 48
#define ASTAGE (BM*PADK)
#define BSTAGE (BN*PADK)
#define NKT (HIDDEN / BK)
#define STAGE_FLOATS (ASTAGE + BSTAGE)
#define GEMM_SMEM (2 * STAGE_FLOATS * 4)

__global__ __launch_bounds__(128, 2) void gemm_mma_kernel(
    const float* __restrict__ A,
    const float* __restrict__ B0, const float* __restrict__ B1, const float* __restrict__ B2,
    float* __restrict__ D0, float* __restrict__ D1, float* __restrict__ D2,
    const float* __restrict__ bias, int mode)
{
    extern __shared__ float sm[];
    const int t    = threadIdx.x;
    const int wid  = t >> 5;
    const int lane = t & 31;
    const int gid  = lane >> 2;
    const int tig  = lane & 3;
    const int z = blockIdx.z;
    const float* __restrict__ B = (z == 0) ? B0 : (z == 1) ? B1 : B2;
    float* __restrict__ D       = (z == 0) ? D0 : (z == 1) ? D1 : D2;
    const int n0 = blockIdx.x * BN;
    const int m0 = blockIdx.y * BM;
    const int wm = (wid & 1) * 64;
    const int wn = (wid >> 1) * 64;

    const uint32_t smb = smem_u32(sm);

    const int ar = t >> 3;           // 0..15 (+16 per iter)
    const int ac = (t & 7) * 4;
    const float* agp = A + (size_t)(m0 + ar) * HIDDEN + ac;
    const float* bgp = B + (size_t)(n0 + ar) * HIDDEN + ac;
    const uint32_t asb = smb + (uint32_t)(ar * PADK + ac) * 4;
    const uint32_t bsb = smb + (uint32_t)(ASTAGE + ar * PADK + ac) * 4;

    float acc[4][8][4];
#pragma unroll
    for (int mi = 0; mi < 4; ++mi)
#pragma unroll
        for (int ni = 0; ni < 8; ++ni)
#pragma unroll
            for (int j = 0; j < 4; ++j) acc[mi][ni][j] = 0.f;

    auto issue = [&](int kt, int s) {
        const uint32_t so = (uint32_t)(s * STAGE_FLOATS) * 4;
        const int ko = kt * BK;
#pragma unroll
        for (int i = 0; i < 8; ++i)
            cpa16(asb + so + (uint32_t)(i * 16 * PADK) * 4, agp + (size_t)i * 16 * HIDDEN + ko);
#pragma unroll
        for (int i = 0; i < 8; ++i)
            cpa16(bsb + so + (uint32_t)(i * 16 * PADK) * 4, bgp + (size_t)i * 16 * HIDDEN + ko);
        CPA_COMMIT();
    };

    issue(0, 0);

    for (int kt = 0; kt < NKT; ++kt) {
        cpa_wait<0>();       // stage kt fully arrived
        __syncthreads();     // all warps done reading stage kt-1
        if (kt + 1 < NKT) issue(kt + 1, (kt + 1) & 1);   // safe: after barrier

        const float* As = sm + (kt & 1) * STAGE_FLOATS;
        const float* Bs = As + ASTAGE;

#pragma unroll
        for (int kp = 0; kp < 2; ++kp) {          // each kp = two k8 mma groups
            const int kk = kp * 16 + 4 * tig;
            uint32_t a0[4][4], a1[4][4], b0[8][2], b1[8][2];
#pragma unroll
            for (int mi = 0; mi < 4; ++mi) {
                const int r = wm + mi * 16 + gid;
                uint4 v0 = *(const uint4*)&As[r * PADK + kk];
                uint4 v1 = *(const uint4*)&As[(r + 8) * PADK + kk];
                a0[mi][0] = v0.x; a0[mi][2] = v0.y;   // group0: k 4t+0, 4t+1
                a0[mi][1] = v1.x; a0[mi][3] = v1.y;
                a1[mi][0] = v0.z; a1[mi][2] = v0.w;   // group1: k 4t+2, 4t+3
                a1[mi][1] = v1.z; a1[mi][3] = v1.w;
            }
#pragma unroll
            for (int ni = 0; ni < 8; ++ni) {
                const int c = wn + ni * 8 + gid;
                uint4 v = *(const uint4*)&Bs[c * PADK + kk];
                b0[ni][0] = v.x; b0[ni][1] = v.y;
                b1[ni][0] = v.z; b1[ni][1] = v.w;
            }
#pragma unroll
            for (int mi = 0; mi < 4; ++mi)
#pragma unroll
                for (int ni = 0; ni < 8; ++ni)
                    mma16n8k8(acc[mi][ni], a0[mi], b0[ni]);
#pragma unroll
            for (int mi = 0; mi < 4; ++mi)
#pragma unroll
                for (int ni = 0; ni < 8; ++ni)
                    mma16n8k8(acc[mi][ni], a1[mi], b1[ni]);
        }
    }

#pragma unroll
    for (int mi = 0; mi < 4; ++mi) {
#pragma unroll
        for (int ni = 0; ni < 8; ++ni) {
            const int c = wn + ni * 8 + 2 * tig;
            const int r0 = wm + mi * 16 + gid;
            const int r1 = r0 + 8;
            float2 v0 = {acc[mi][ni][0], acc[mi][ni][1]};
            float2 v1 = {acc[mi][ni][2], acc[mi][ni][3]};
            if (mode == 0) {
                float2 bb = *(const float2*)&bias[n0 + c];
                v0.x += bb.x; v0.y += bb.y;
                v1.x += bb.x; v1.y += bb.y;
                *(float2*)&D[(size_t)(m0 + r0) * HIDDEN + n0 + c] = v0;
                *(float2*)&D[(size_t)(m0 + r1) * HIDDEN + n0 + c] = v1;
            } else {
                const int h = blockIdx.x;
                int m = m0 + r0;
                int bb0 = m >> 10, s0q = m & 1023;
                *(float2*)&D[(((size_t)(bb0 * HEADS + h) * SEQ + s0q) << 7) + c] = v0;
                m = m0 + r1;
                int bb1 = m >> 10, s1q = m & 1023;
                *(float2*)&D[(((size_t)(bb1 * HEADS + h) * SEQ + s1q) << 7) + c] = v1;
            }
        }
    }
}

// ============================================================================
// K2: RoPE in place on q,k; k,v rounded to tf32 (flash MMA operands)
// ============================================================================
__global__ void rope_kernel(float* __restrict__ q, float* __restrict__ k, float* __restrict__ v)
{
    int idx = blockIdx.x * blockDim.x + threadIdx.x;
    if (idx >= BATCH * HEADS * SEQ * 64) return;
    int i  = idx & 63;
    int s  = (idx >> 6) & (SEQ - 1);
    int bh = idx >> 16;

    float inv = expf(-(float)(2 * i) * (9.210340371976184f / 128.f));
    float th  = (float)s * inv;
    float sn, cs;
    sincosf(th, &sn, &cs);

    size_t base = ((size_t)bh * SEQ + s) * HEAD_DIM + i;
    float q1 = q[base], q2 = q[base + 64];
    q[base]      = q1 * cs - q2 * sn;        // full fp32 (split in flash)
    q[base + 64] = q2 * cs + q1 * sn;
    float k1 = k[base], k2 = k[base + 64];
    k[base]      = to_tf32(k1 * cs - k2 * sn);
    k[base + 64] = to_tf32(k2 * cs + k1 * sn);
    v[base]      = to_tf32(v[base]);
    v[base + 64] = to_tf32(v[base + 64]);
}

// ============================================================================
// K3: causal flash attention (R9 version — proven best at 238us).
// 512 threads, 16 warps (4m x 4n), split-Q hi/lo, double-buffered KV,
// race-safe pipeline, LDS.64 slice-permuted fragments, smem P.
// ============================================================================
#define FPADD 136
#define FPADV 132
#define FPADP 72
#define OQH  0
#define OQL  8704
#define OKS  17408
#define OVS  34816
#define OPS  51712
#define ORM  56320
#define ORL  56384
#define ORDM 56448
#define ORDS 56704
#define FLASH_FLOATS 56960
#define FLASH_SMEM (FLASH_FLOATS * 4)

__global__ __launch_bounds__(512, 1) void flash_kernel(
    const float* __restrict__ q, const float* __restrict__ k, const float* __restrict__ v,
    const float* __restrict__ pm, const float* __restrict__ pol, const float* __restrict__ mw,
    float* __restrict__ attn)
{
    extern __shared__ float smf[];
    const uint32_t smb = smem_u32(smf);

    const int t    = threadIdx.x;
    const int wid  = t >> 5;
    const int lane = t & 31;
    const int gid  = lane >> 2;
    const int tig  = lane & 3;
    const int wm   = (wid & 3) * 16;
    const int wni  = wid >> 2;
    const int wn   = wni * 16;
    const int wd   = wni * 32;

    const int qt = (gridDim.x - 1) - blockIdx.x;
    const int bh = blockIdx.y;
    const int q0 = qt * 64;

    const float* qb = q + (size_t)bh * SEQ * HEAD_DIM;
    const float* kb = k + (size_t)bh * SEQ * HEAD_DIM;
    const float* vb = v + (size_t)bh * SEQ * HEAD_DIM;
    const size_t moff = (size_t)bh * SEQ * SEQ;

    for (int idx = t; idx < 64 * 32; idx += 512) {
        int r  = idx >> 5;
        int c4 = (idx & 31) * 4;
        float4 x = *(const float4*)&qb[(size_t)(q0 + r) * HEAD_DIM + c4];
        float* qh = smf + OQH + r * FPADD + c4;
        float* ql = smf + OQL + r * FPADD + c4;
        float h0 = to_tf32(x.x); qh[0] = h0; ql[0] = to_tf32(x.x - h0);
        float h1 = to_tf32(x.y); qh[1] = h1; ql[1] = to_tf32(x.y - h1);
        float h2 = to_tf32(x.z); qh[2] = h2; ql[2] = to_tf32(x.z - h2);
        float h3 = to_tf32(x.w); qh[3] = h3; ql[3] = to_tf32(x.w - h3);
    }
    if (t < 64) { smf[ORM + t] = -1e30f; smf[ORL + t] = 0.f; }

    auto issueKV = [&](int jt, int s) {
        const int j0 = jt * 64;
#pragma unroll
        for (int i = 0; i < 4; ++i) {
            int idx = i * 512 + t;
            int r  = idx >> 5;
            int c4 = (idx & 31) * 4;
            cpa16(smb + (uint32_t)(OKS + s * 8704 + r * FPADD + c4) * 4,
                  &kb[(size_t)(j0 + r) * HEAD_DIM + c4]);
            cpa16(smb + (uint32_t)(OVS + s * 8448 + r * FPADV + c4) * 4,
                  &vb[(size_t)(j0 + r) * HEAD_DIM + c4]);
        }
        CPA_COMMIT();
    };

    issueKV(0, 0);

    const float SC2  = 0.08838834764831845f * 1.4426950408889634f;
    const float CPM  = 0.05f * 1.4426950408889634f;
    const float CPO  = 0.1f  * 1.4426950408889634f;

    const int row0  = wm + gid;
    const int row1  = row0 + 8;
    const int grow0 = q0 + row0;
    const int grow1 = q0 + row1;

    float acc_o[4][4];
#pragma unroll
    for (int ni = 0; ni < 4; ++ni)
#pragma unroll
        for (int j = 0; j < 4; ++j) acc_o[ni][j] = 0.f;

    for (int jt = 0; jt <= qt; ++jt) {
        cpa_wait<0>();
        __syncthreads();   // #1: KV stage jt ready; prev iteration fully done
        if (jt < qt) issueKV(jt + 1, (jt + 1) & 1);   // safe: after barrier

        const float* Kb = smf + OKS + (jt & 1) * 8704;
        const float* Vb = smf + OVS + (jt & 1) * 8448;
        const int j0c = jt * 64;

        const size_t mr0 = moff + (size_t)grow0 * SEQ + j0c;
        const size_t mr1 = moff + (size_t)grow1 * SEQ + j0c;
        float2 pa0[2], pb0[2], pc0[2], pa1[2], pb1[2], pc1[2];
#pragma unroll
        for (int ni = 0; ni < 2; ++ni) {
            const int cl = wn + ni * 8 + 2 * tig;
            pa0[ni] = *(const float2*)&pm[mr0 + cl];
            pb0[ni] = *(const float2*)&pol[mr0 + cl];
            pc0[ni] = *(const float2*)&mw[mr0 + cl];
            pa1[ni] = *(const float2*)&pm[mr1 + cl];
            pb1[ni] = *(const float2*)&pol[mr1 + cl];
            pc1[ni] = *(const float2*)&mw[mr1 + cl];
        }

        float accs[2][4];
#pragma unroll
        for (int ni = 0; ni < 2; ++ni)
#pragma unroll
            for (int j = 0; j < 4; ++j) accs[ni][j] = 0.f;

#pragma unroll
        for (int ks = 0; ks < 16; ++ks) {
            const int kk = ks * 8 + 2 * tig;
            uint32_t ah[4], al[4], b[2][2];
            uint2 h0 = *(const uint2*)&smf[OQH + row0 * FPADD + kk];
            uint2 h1 = *(const uint2*)&smf[OQH + row1 * FPADD + kk];
            uint2 l0 = *(const uint2*)&smf[OQL + row0 * FPADD + kk];
            uint2 l1 = *(const uint2*)&smf[OQL + row1 * FPADD + kk];
            ah[0] = h0.x; ah[2] = h0.y; ah[1] = h1.x; ah[3] = h1.y;
            al[0] = l0.x; al[2] = l0.y; al[1] = l1.x; al[3] = l1.y;
#pragma unroll
            for (int ni = 0; ni < 2; ++ni) {
                const int c = wn + ni * 8 + gid;
                uint2 bv = *(const uint2*)&Kb[c * FPADD + kk];
                b[ni][0] = bv.x; b[ni][1] = bv.y;
            }
#pragma unroll
            for (int ni = 0; ni < 2; ++ni) {
                mma16n8k8(accs[ni], ah, b[ni]);
                mma16n8k8(accs[ni], al, b[ni]);
            }
        }

        const bool diag = (jt == qt);
        float ml0 = -1e30f, ml1 = -1e30f;
#pragma unroll
        for (int ni = 0; ni < 2; ++ni) {
            const int cl = wn + ni * 8 + 2 * tig;
            float s0 = fmaf(accs[ni][0], SC2, fmaf(pa0[ni].x, CPM, fmaf(pb0[ni].x, CPO, log2p_small(fmaf(pc0[ni].x, 0.1f, 1e-8f)))));
            float s1 = fmaf(accs[ni][1], SC2, fmaf(pa0[ni].y, CPM, fmaf(pb0[ni].y, CPO, log2p_small(fmaf(pc0[ni].y, 0.1f, 1e-8f)))));
            float s2 = fmaf(accs[ni][2], SC2, fmaf(pa1[ni].x, CPM, fmaf(pb1[ni].x, CPO, log2p_small(fmaf(pc1[ni].x, 0.1f, 1e-8f)))));
            float s3 = fmaf(accs[ni][3], SC2, fmaf(pa1[ni].y, CPM, fmaf(pb1[ni].y, CPO, log2p_small(fmaf(pc1[ni].y, 0.1f, 1e-8f)))));
            if (diag) {
                if (cl     > row0) s0 = -1e30f;
                if (cl + 1 > row0) s1 = -1e30f;
                if (cl     > row1) s2 = -1e30f;
                if (cl + 1 > row1) s3 = -1e30f;
            }
            accs[ni][0] = s0; accs[ni][1] = s1; accs[ni][2] = s2; accs[ni][3] = s3;
            ml0 = fmaxf(ml0, fmaxf(s0, s1));
            ml1 = fmaxf(ml1, fmaxf(s2, s3));
        }
#pragma unroll
        for (int o = 1; o < 4; o <<= 1) {
            ml0 = fmaxf(ml0, __shfl_xor_sync(0xffffffffu, ml0, o));
            ml1 = fmaxf(ml1, __shfl_xor_sync(0xffffffffu, ml1, o));
        }
        if (tig == 0) {
            smf[ORDM + wni * 64 + row0] = ml0;
            smf[ORDM + wni * 64 + row1] = ml1;
        }
        float mold0 = smf[ORM + row0];
        float mold1 = smf[ORM + row1];
        __syncthreads();   // #2: redm ready

        float mn0 = fmaxf(fmaxf(mold0, fmaxf(smf[ORDM + row0], smf[ORDM + 64 + row0])),
                          fmaxf(smf[ORDM + 128 + row0], smf[ORDM + 192 + row0]));
        float mn1 = fmaxf(fmaxf(mold1, fmaxf(smf[ORDM + row1], smf[ORDM + 64 + row1])),
                          fmaxf(smf[ORDM + 128 + row1], smf[ORDM + 192 + row1]));
        float al0 = exp2c(mold0 - mn0);
        float al1 = exp2c(mold1 - mn1);

        float sum0 = 0.f, sum1 = 0.f;
#pragma unroll
        for (int ni = 0; ni < 2; ++ni) {
            const int cl = wn + ni * 8 + 2 * tig;
            float p0 = exp2c(accs[ni][0] - mn0);
            float p1 = exp2c(accs[ni][1] - mn0);
            float p2 = exp2c(accs[ni][2] - mn1);
            float p3 = exp2c(accs[ni][3] - mn1);
            sum0 += p0 + p1;
            sum1 += p2 + p3;
            smf[OPS + row0 * FPADP + cl]     = to_tf32(p0);
            smf[OPS + row0 * FPADP + cl + 1] = to_tf32(p1);
            smf[OPS + row1 * FPADP + cl]     = to_tf32(p2);
            smf[OPS + row1 * FPADP + cl + 1] = to_tf32(p3);
        }
#pragma unroll
        for (int o = 1; o < 4; o <<= 1) {
            sum0 += __shfl_xor_sync(0xffffffffu, sum0, o);
            sum1 += __shfl_xor_sync(0xffffffffu, sum1, o);
        }
        if (tig == 0) {
            smf[ORDS + wni * 64 + row0] = sum0;
            smf[ORDS + wni * 64 + row1] = sum1;
        }
#pragma unroll
        for (int ni = 0; ni < 4; ++ni) {
            acc_o[ni][0] *= al0; acc_o[ni][1] *= al0;
            acc_o[ni][2] *= al1; acc_o[ni][3] *= al1;
        }
        __syncthreads();   // #3: Ps + reds ready

        if (t < 64) {
            float mo = smf[ORM + t];
            float mn = fmaxf(fmaxf(mo, fmaxf(smf[ORDM + t], smf[ORDM + 64 + t])),
                             fmaxf(smf[ORDM + 128 + t], smf[ORDM + 192 + t]));
            float a  = exp2c(mo - mn);
            smf[ORL + t] = smf[ORL + t] * a
                         + smf[ORDS + t] + smf[ORDS + 64 + t]
                         + smf[ORDS + 128 + t] + smf[ORDS + 192 + t];
            smf[ORM + t] = mn;
        }

        const float* Pu = smf + OPS;
        const float* Vu = Vb;
#pragma unroll
        for (int ks = 0; ks < 8; ++ks) {
            const int kk = ks * 8 + 2 * tig;
            uint32_t a[4], b[4][2];
            uint2 p0 = *(const uint2*)&Pu[row0 * FPADP + kk];
            uint2 p1 = *(const uint2*)&Pu[row1 * FPADP + kk];
            a[0] = p0.x; a[2] = p0.y; a[1] = p1.x; a[3] = p1.y;
#pragma unroll
            for (int ni = 0; ni < 4; ++ni) {
                const int c = wd + ni * 8 + gid;
                b[ni][0] = *(const uint32_t*)&Vu[kk * FPADV + c];
                b[ni][1] = *(const uint32_t*)&Vu[(kk + 1) * FPADV + c];
            }
#pragma unroll
            for (int ni = 0; ni < 4; ++ni)
                mma16n8k8(acc_o[ni], a, b[ni]);
        }
    }

    __syncthreads();
    const float l0 = 1.f / smf[ORL + row0];
    const float l1 = 1.f / smf[ORL + row1];
    const int bb = bh >> 4;
    const int h  = bh & 15;
    float* o0 = attn + ((size_t)(bb * SEQ + grow0)) * HIDDEN + h * HEAD_DIM;
    float* o1 = attn + ((size_t)(bb * SEQ + grow1)) * HIDDEN + h * HEAD_DIM;
#pragma unroll
    for (int ni = 0; ni < 4; ++ni) {
        const int d = wd + ni * 8 + 2 * tig;
        float2 w0 = {to_tf32(acc_o[ni][0] * l0), to_tf32(acc_o[ni][1] * l0)};
        float2 w1 = {to_tf32(acc_o[ni][2] * l1), to_tf32(acc_o[ni][3] * l1)};
        *(float2*)(o0 + d) = w0;
        *(float2*)(o1 + d) = w1;
    }
}

// ============================================================================
// host launcher
// ============================================================================
extern "C" void kernel_launch(void* const* d_in, const int* in_sizes, int n_in,
                              void* d_out, int out_size)
{
    const float* x   = (const float*)d_in[0];
    const float* pm  = (const float*)d_in[1];
    const float* pol = (const float*)d_in[2];
    const float* mw  = (const float*)d_in[3];
    const float* Wq  = (const float*)d_in[4];
    const float* Wk  = (const float*)d_in[5];
    const float* Wv  = (const float*)d_in[6];
    const float* Wo  = (const float*)d_in[7];
    const float* bo  = (const float*)d_in[8];
    float* out = (float*)d_out;

    float *gq, *gk, *gv, *ga, *gw, *gx;
    cudaGetSymbolAddress((void**)&gq, g_q);
    cudaGetSymbolAddress((void**)&gk, g_k);
    cudaGetSymbolAddress((void**)&gv, g_v);
    cudaGetSymbolAddress((void**)&ga, g_attn);
    cudaGetSymbolAddress((void**)&gw, g_wt);
    cudaGetSymbolAddress((void**)&gx, g_xc);

    cudaFuncSetAttribute(flash_kernel,
                         cudaFuncAttributeMaxDynamicSharedMemorySize, FLASH_SMEM);
    cudaFuncSetAttribute(gemm_mma_kernel,
                         cudaFuncAttributeMaxDynamicSharedMemorySize, GEMM_SMEM);

    float* wtq = gw;
    float* wtk = gw + (size_t)HIDDEN * HIDDEN;
    float* wtv = gw + 2 * (size_t)HIDDEN * HIDDEN;
    float* wto = gw + 3 * (size_t)HIDDEN * HIDDEN;

    const int n4 = HIDDEN * HIDDEN / 4;
    cvt_tf32_kernel<<<(n4 + 255) / 256, 256>>>(x, gx, n4);
    transpose2048<<<dim3(64, 64, 4), 256>>>(Wq, Wk, Wv, Wo, gw);

    // K1: QKV projections (LDS.128 double-pair GEMM)
    gemm_mma_kernel<<<dim3(HIDDEN / BN, MROWS / BM, 3), 128, GEMM_SMEM>>>(
        gx, wtq, wtk, wtv, gq, gk, gv, nullptr, 1);

    // K2: RoPE + tf32 rounding of k, v
    int rope_n = BATCH * HEADS * SEQ * 64;
    rope_kernel<<<(rope_n + 255) / 256, 256>>>(gq, gk, gv);

    // K3: tensor-core flash attention (R9 version)
    dim3 gfl(SEQ / 64, BATCH * HEADS);
    flash_kernel<<<gfl, 512, FLASH_SMEM>>>(gq, gk, gv, pm, pol, mw, ga);

    // K4: output projection + bias
    gemm_mma_kernel<<<dim3(HIDDEN / BN, MROWS / BM, 1), 128, GEMM_SMEM>>>(
        ga, wto, wto, wto, out, out, out, bo, 0);
}

// round 15
// speedup vs baseline: 1.0452x; 1.0452x over previous
#include <cuda_runtime.h>
#include <math.h>
#include <stdint.h>

#define HIDDEN   2048
#define HEADS    16
#define HEAD_DIM 128
#define BATCH    2
#define SEQ      1024
#define MROWS    (BATCH*SEQ)

// ---------------- scratch (allocation-free: device globals) ----------------
__device__ float g_q[BATCH*HEADS*SEQ*HEAD_DIM];
__device__ float g_k[BATCH*HEADS*SEQ*HEAD_DIM];
__device__ float g_v[BATCH*HEADS*SEQ*HEAD_DIM];
__device__ float g_attn[MROWS*HIDDEN];
__device__ float g_xc[MROWS*HIDDEN];        // tf32-rounded x
__device__ float g_wt[4*HIDDEN*HIDDEN];     // tf32-rounded transposed weights [N,K]

// ============================================================================
// helpers
// ============================================================================
__device__ __forceinline__ uint32_t smem_u32(const void* p) {
    uint32_t a;
    asm("{ .reg .u64 t; cvta.to.shared.u64 t, %1; cvt.u32.u64 %0, t; }"
        : "=r"(a) : "l"(p));
    return a;
}
__device__ __forceinline__ float to_tf32(float x) {
    uint32_t u;
    asm("cvt.rna.tf32.f32 %0, %1;" : "=r"(u) : "f"(x));
    return __uint_as_float(u);
}
__device__ __forceinline__ void cpa16(uint32_t s, const void* g) {
    asm volatile("cp.async.cg.shared.global [%0], [%1], 16;" :: "r"(s), "l"(g));
}
#define CPA_COMMIT() asm volatile("cp.async.commit_group;" ::: "memory")
template<int N> __device__ __forceinline__ void cpa_wait() {
    asm volatile("cp.async.wait_group %0;" :: "n"(N) : "memory");
}
__device__ __forceinline__ void mma16n8k8(float* c, const uint32_t* a, const uint32_t* b) {
    asm volatile(
        "mma.sync.aligned.m16n8k8.row.col.f32.tf32.tf32.f32 "
        "{%0,%1,%2,%3}, {%4,%5,%6,%7}, {%8,%9}, {%0,%1,%2,%3};"
        : "+f"(c[0]), "+f"(c[1]), "+f"(c[2]), "+f"(c[3])
        : "r"(a[0]), "r"(a[1]), "r"(a[2]), "r"(a[3]), "r"(b[0]), "r"(b[1]));
}

// 2^x via FMA-pipe polynomial (no MUFU)
__device__ __forceinline__ float exp2c(float x) {
    x = fmaxf(x, -126.f);
    float fl = floorf(x);
    float f  = x - fl;
    int   i  = (int)fl;
    float r = 1.52527338e-5f;
    r = fmaf(r, f, 1.54035304e-4f);
    r = fmaf(r, f, 1.33335581e-3f);
    r = fmaf(r, f, 9.61812911e-3f);
    r = fmaf(r, f, 5.55041087e-2f);
    r = fmaf(r, f, 2.40226507e-1f);
    r = fmaf(r, f, 6.93147181e-1f);
    r = fmaf(r, f, 1.0f);
    return r * __int_as_float((i + 127) << 23);
}
// log2(1+u) for u in [0, ~0.101]
__device__ __forceinline__ float log2p_small(float u) {
    float r = 0.14285714f;
    r = fmaf(r, u, -0.16666667f);
    r = fmaf(r, u, 0.2f);
    r = fmaf(r, u, -0.25f);
    r = fmaf(r, u, 0.33333333f);
    r = fmaf(r, u, -0.5f);
    r = fmaf(r, u, 1.0f);
    return r * u * 1.4426950408889634f;
}

// ============================================================================
// K0: combined prep — z<4: transpose+round W[K,N]->Wt[N,K]; z==4: round x.
// grid (64, 64, 5), 256 threads.
// ============================================================================
__global__ void prep_kernel(
    const float* __restrict__ x,
    const float* __restrict__ s0, const float* __restrict__ s1,
    const float* __restrict__ s2, const float* __restrict__ s3,
    float* __restrict__ gx, float* __restrict__ dst)
{
    int z = blockIdx.z;
    if (z == 4) {
        int i = ((blockIdx.y * 64 + blockIdx.x) * 256 + threadIdx.x);
        float4 v = ((const float4*)x)[i];
        v.x = to_tf32(v.x); v.y = to_tf32(v.y);
        v.z = to_tf32(v.z); v.w = to_tf32(v.w);
        ((float4*)gx)[i] = v;
        return;
    }
    __shared__ float tile[32][33];
    const float* src = (z == 0) ? s0 : (z == 1) ? s1 : (z == 2) ? s2 : s3;
    float* d = dst + (size_t)z * HIDDEN * HIDDEN;
    int tx = threadIdx.x & 31, ty = threadIdx.x >> 5;
    int xx = blockIdx.x * 32 + tx, y0 = blockIdx.y * 32 + ty;
#pragma unroll
    for (int j = 0; j < 4; ++j)
        tile[ty + j * 8][tx] = to_tf32(src[(size_t)(y0 + j * 8) * HIDDEN + xx]);
    __syncthreads();
    int x2 = blockIdx.y * 32 + tx, y2 = blockIdx.x * 32 + ty;
#pragma unroll
    for (int j = 0; j < 4; ++j)
        d[(size_t)(y2 + j * 8) * HIDDEN + x2] = tile[tx][ty + j * 8];
}

// ============================================================================
// K1/K4: tf32 mma.sync GEMM (R9 config: CTA 128x128, 4 warps 64x64, 2-stage,
// LDS.64 slice-permuted fragment loads, PADK=40, 2 CTAs/SM)
// ============================================================================
#define BM 128
#define BN 128
#define BK 32
#define PADK 40
#define ASTAGE (BM*PADK)
#define BSTAGE (BN*PADK)
#define NKT (HIDDEN / BK)
#define STAGE_FLOATS (ASTAGE + BSTAGE)
#define GEMM_SMEM (2 * STAGE_FLOATS * 4)

__global__ __launch_bounds__(128, 2) void gemm_mma_kernel(
    const float* __restrict__ A,
    const float* __restrict__ B0, const float* __restrict__ B1, const float* __restrict__ B2,
    float* __restrict__ D0, float* __restrict__ D1, float* __restrict__ D2,
    const float* __restrict__ bias, int mode)
{
    extern __shared__ float sm[];
    const int t    = threadIdx.x;
    const int wid  = t >> 5;
    const int lane = t & 31;
    const int gid  = lane >> 2;
    const int tig  = lane & 3;
    const int z = blockIdx.z;
    const float* __restrict__ B = (z == 0) ? B0 : (z == 1) ? B1 : B2;
    float* __restrict__ D       = (z == 0) ? D0 : (z == 1) ? D1 : D2;
    const int n0 = blockIdx.x * BN;
    const int m0 = blockIdx.y * BM;
    const int wm = (wid & 1) * 64;
    const int wn = (wid >> 1) * 64;

    const uint32_t smb = smem_u32(sm);

    const int ar = t >> 3;
    const int ac = (t & 7) * 4;
    const float* agp = A + (size_t)(m0 + ar) * HIDDEN + ac;
    const float* bgp = B + (size_t)(n0 + ar) * HIDDEN + ac;
    const uint32_t asb = smb + (uint32_t)(ar * PADK + ac) * 4;
    const uint32_t bsb = smb + (uint32_t)(ASTAGE + ar * PADK + ac) * 4;

    float acc[4][8][4];
#pragma unroll
    for (int mi = 0; mi < 4; ++mi)
#pragma unroll
        for (int ni = 0; ni < 8; ++ni)
#pragma unroll
            for (int j = 0; j < 4; ++j) acc[mi][ni][j] = 0.f;

    auto issue = [&](int kt, int s) {
        const uint32_t so = (uint32_t)(s * STAGE_FLOATS) * 4;
        const int ko = kt * BK;
#pragma unroll
        for (int i = 0; i < 8; ++i)
            cpa16(asb + so + (uint32_t)(i * 16 * PADK) * 4, agp + (size_t)i * 16 * HIDDEN + ko);
#pragma unroll
        for (int i = 0; i < 8; ++i)
            cpa16(bsb + so + (uint32_t)(i * 16 * PADK) * 4, bgp + (size_t)i * 16 * HIDDEN + ko);
        CPA_COMMIT();
    };

    issue(0, 0);

    for (int kt = 0; kt < NKT; ++kt) {
        cpa_wait<0>();
        __syncthreads();
        if (kt + 1 < NKT) issue(kt + 1, (kt + 1) & 1);

        const float* As = sm + (kt & 1) * STAGE_FLOATS;
        const float* Bs = As + ASTAGE;

#pragma unroll
        for (int ks = 0; ks < 4; ++ks) {
            const int kk = ks * 8 + 2 * tig;
            uint32_t a[4][4], b[8][2];
#pragma unroll
            for (int mi = 0; mi < 4; ++mi) {
                const int r = wm + mi * 16 + gid;
                uint2 v0 = *(const uint2*)&As[r * PADK + kk];
                uint2 v1 = *(const uint2*)&As[(r + 8) * PADK + kk];
                a[mi][0] = v0.x; a[mi][2] = v0.y;
                a[mi][1] = v1.x; a[mi][3] = v1.y;
            }
#pragma unroll
            for (int ni = 0; ni < 8; ++ni) {
                const int c = wn + ni * 8 + gid;
                uint2 v = *(const uint2*)&Bs[c * PADK + kk];
                b[ni][0] = v.x; b[ni][1] = v.y;
            }
#pragma unroll
            for (int mi = 0; mi < 4; ++mi)
#pragma unroll
                for (int ni = 0; ni < 8; ++ni)
                    mma16n8k8(acc[mi][ni], a[mi], b[ni]);
        }
    }

#pragma unroll
    for (int mi = 0; mi < 4; ++mi) {
#pragma unroll
        for (int ni = 0; ni < 8; ++ni) {
            const int c = wn + ni * 8 + 2 * tig;
            const int r0 = wm + mi * 16 + gid;
            const int r1 = r0 + 8;
            float2 v0 = {acc[mi][ni][0], acc[mi][ni][1]};
            float2 v1 = {acc[mi][ni][2], acc[mi][ni][3]};
            if (mode == 0) {
                float2 bb = *(const float2*)&bias[n0 + c];
                v0.x += bb.x; v0.y += bb.y;
                v1.x += bb.x; v1.y += bb.y;
                *(float2*)&D[(size_t)(m0 + r0) * HIDDEN + n0 + c] = v0;
                *(float2*)&D[(size_t)(m0 + r1) * HIDDEN + n0 + c] = v1;
            } else {
                const int h = blockIdx.x;
                int m = m0 + r0;
                int bb0 = m >> 10, s0q = m & 1023;
                *(float2*)&D[(((size_t)(bb0 * HEADS + h) * SEQ + s0q) << 7) + c] = v0;
                m = m0 + r1;
                int bb1 = m >> 10, s1q = m & 1023;
                *(float2*)&D[(((size_t)(bb1 * HEADS + h) * SEQ + s1q) << 7) + c] = v1;
            }
        }
    }
}

// ============================================================================
// K2: RoPE in place (float2: each thread rotates 2 adjacent dim-pairs)
// ============================================================================
__global__ void rope_kernel(float* __restrict__ q, float* __restrict__ k, float* __restrict__ v)
{
    int idx = blockIdx.x * blockDim.x + threadIdx.x;
    if (idx >= BATCH * HEADS * SEQ * 32) return;
    int i2 = (idx & 31) * 2;                 // dim pair base: 0,2,...,62
    int s  = (idx >> 5) & (SEQ - 1);
    int bh = idx >> 15;

    float inv0 = expf(-(float)(2 * i2)     * (9.210340371976184f / 128.f));
    float inv1 = expf(-(float)(2 * i2 + 2) * (9.210340371976184f / 128.f));
    float sn0, cs0, sn1, cs1;
    sincosf((float)s * inv0, &sn0, &cs0);
    sincosf((float)s * inv1, &sn1, &cs1);

    size_t base = ((size_t)bh * SEQ + s) * HEAD_DIM + i2;
    float2 q1 = *(float2*)&q[base];
    float2 q2 = *(float2*)&q[base + 64];
    float2 k1 = *(float2*)&k[base];
    float2 k2 = *(float2*)&k[base + 64];
    float2 v1 = *(float2*)&v[base];
    float2 v2 = *(float2*)&v[base + 64];

    float2 qo1 = {q1.x * cs0 - q2.x * sn0, q1.y * cs1 - q2.y * sn1};
    float2 qo2 = {q2.x * cs0 + q1.x * sn0, q2.y * cs1 + q1.y * sn1};
    *(float2*)&q[base]      = qo1;          // full fp32 (split in flash)
    *(float2*)&q[base + 64] = qo2;

    float2 ko1 = {to_tf32(k1.x * cs0 - k2.x * sn0), to_tf32(k1.y * cs1 - k2.y * sn1)};
    float2 ko2 = {to_tf32(k2.x * cs0 + k1.x * sn0), to_tf32(k2.y * cs1 + k1.y * sn1)};
    *(float2*)&k[base]      = ko1;
    *(float2*)&k[base + 64] = ko2;

    v1.x = to_tf32(v1.x); v1.y = to_tf32(v1.y);
    v2.x = to_tf32(v2.x); v2.y = to_tf32(v2.y);
    *(float2*)&v[base]      = v1;
    *(float2*)&v[base + 64] = v2;
}

// ============================================================================
// K3: causal flash attention (R9 version — proven best at 238us).
// 512 threads, 16 warps (4m x 4n), split-Q hi/lo, double-buffered KV,
// race-safe pipeline, LDS.64 slice-permuted fragments, smem P.
// ============================================================================
#define FPADD 136
#define FPADV 132
#define FPADP 72
#define OQH  0
#define OQL  8704
#define OKS  17408
#define OVS  34816
#define OPS  51712
#define ORM  56320
#define ORL  56384
#define ORDM 56448
#define ORDS 56704
#define FLASH_FLOATS 56960
#define FLASH_SMEM (FLASH_FLOATS * 4)

__global__ __launch_bounds__(512, 1) void flash_kernel(
    const float* __restrict__ q, const float* __restrict__ k, const float* __restrict__ v,
    const float* __restrict__ pm, const float* __restrict__ pol, const float* __restrict__ mw,
    float* __restrict__ attn)
{
    extern __shared__ float smf[];
    const uint32_t smb = smem_u32(smf);

    const int t    = threadIdx.x;
    const int wid  = t >> 5;
    const int lane = t & 31;
    const int gid  = lane >> 2;
    const int tig  = lane & 3;
    const int wm   = (wid & 3) * 16;
    const int wni  = wid >> 2;
    const int wn   = wni * 16;
    const int wd   = wni * 32;

    const int qt = (gridDim.x - 1) - blockIdx.x;
    const int bh = blockIdx.y;
    const int q0 = qt * 64;

    const float* qb = q + (size_t)bh * SEQ * HEAD_DIM;
    const float* kb = k + (size_t)bh * SEQ * HEAD_DIM;
    const float* vb = v + (size_t)bh * SEQ * HEAD_DIM;
    const size_t moff = (size_t)bh * SEQ * SEQ;

    for (int idx = t; idx < 64 * 32; idx += 512) {
        int r  = idx >> 5;
        int c4 = (idx & 31) * 4;
        float4 x = *(const float4*)&qb[(size_t)(q0 + r) * HEAD_DIM + c4];
        float* qh = smf + OQH + r * FPADD + c4;
        float* ql = smf + OQL + r * FPADD + c4;
        float h0 = to_tf32(x.x); qh[0] = h0; ql[0] = to_tf32(x.x - h0);
        float h1 = to_tf32(x.y); qh[1] = h1; ql[1] = to_tf32(x.y - h1);
        float h2 = to_tf32(x.z); qh[2] = h2; ql[2] = to_tf32(x.z - h2);
        float h3 = to_tf32(x.w); qh[3] = h3; ql[3] = to_tf32(x.w - h3);
    }
    if (t < 64) { smf[ORM + t] = -1e30f; smf[ORL + t] = 0.f; }

    auto issueKV = [&](int jt, int s) {
        const int j0 = jt * 64;
#pragma unroll
        for (int i = 0; i < 4; ++i) {
            int idx = i * 512 + t;
            int r  = idx >> 5;
            int c4 = (idx & 31) * 4;
            cpa16(smb + (uint32_t)(OKS + s * 8704 + r * FPADD + c4) * 4,
                  &kb[(size_t)(j0 + r) * HEAD_DIM + c4]);
            cpa16(smb + (uint32_t)(OVS + s * 8448 + r * FPADV + c4) * 4,
                  &vb[(size_t)(j0 + r) * HEAD_DIM + c4]);
        }
        CPA_COMMIT();
    };

    issueKV(0, 0);

    const float SC2  = 0.08838834764831845f * 1.4426950408889634f;
    const float CPM  = 0.05f * 1.4426950408889634f;
    const float CPO  = 0.1f  * 1.4426950408889634f;

    const int row0  = wm + gid;
    const int row1  = row0 + 8;
    const int grow0 = q0 + row0;
    const int grow1 = q0 + row1;

    float acc_o[4][4];
#pragma unroll
    for (int ni = 0; ni < 4; ++ni)
#pragma unroll
        for (int j = 0; j < 4; ++j) acc_o[ni][j] = 0.f;

    for (int jt = 0; jt <= qt; ++jt) {
        cpa_wait<0>();
        __syncthreads();   // #1: KV stage jt ready; prev iteration fully done
        if (jt < qt) issueKV(jt + 1, (jt + 1) & 1);   // safe: after barrier

        const float* Kb = smf + OKS + (jt & 1) * 8704;
        const float* Vb = smf + OVS + (jt & 1) * 8448;
        const int j0c = jt * 64;

        const size_t mr0 = moff + (size_t)grow0 * SEQ + j0c;
        const size_t mr1 = moff + (size_t)grow1 * SEQ + j0c;
        float2 pa0[2], pb0[2], pc0[2], pa1[2], pb1[2], pc1[2];
#pragma unroll
        for (int ni = 0; ni < 2; ++ni) {
            const int cl = wn + ni * 8 + 2 * tig;
            pa0[ni] = *(const float2*)&pm[mr0 + cl];
            pb0[ni] = *(const float2*)&pol[mr0 + cl];
            pc0[ni] = *(const float2*)&mw[mr0 + cl];
            pa1[ni] = *(const float2*)&pm[mr1 + cl];
            pb1[ni] = *(const float2*)&pol[mr1 + cl];
            pc1[ni] = *(const float2*)&mw[mr1 + cl];
        }

        float accs[2][4];
#pragma unroll
        for (int ni = 0; ni < 2; ++ni)
#pragma unroll
            for (int j = 0; j < 4; ++j) accs[ni][j] = 0.f;

#pragma unroll
        for (int ks = 0; ks < 16; ++ks) {
            const int kk = ks * 8 + 2 * tig;
            uint32_t ah[4], al[4], b[2][2];
            uint2 h0 = *(const uint2*)&smf[OQH + row0 * FPADD + kk];
            uint2 h1 = *(const uint2*)&smf[OQH + row1 * FPADD + kk];
            uint2 l0 = *(const uint2*)&smf[OQL + row0 * FPADD + kk];
            uint2 l1 = *(const uint2*)&smf[OQL + row1 * FPADD + kk];
            ah[0] = h0.x; ah[2] = h0.y; ah[1] = h1.x; ah[3] = h1.y;
            al[0] = l0.x; al[2] = l0.y; al[1] = l1.x; al[3] = l1.y;
#pragma unroll
            for (int ni = 0; ni < 2; ++ni) {
                const int c = wn + ni * 8 + gid;
                uint2 bv = *(const uint2*)&Kb[c * FPADD + kk];
                b[ni][0] = bv.x; b[ni][1] = bv.y;
            }
#pragma unroll
            for (int ni = 0; ni < 2; ++ni) {
                mma16n8k8(accs[ni], ah, b[ni]);
                mma16n8k8(accs[ni], al, b[ni]);
            }
        }

        const bool diag = (jt == qt);
        float ml0 = -1e30f, ml1 = -1e30f;
#pragma unroll
        for (int ni = 0; ni < 2; ++ni) {
            const int cl = wn + ni * 8 + 2 * tig;
            float s0 = fmaf(accs[ni][0], SC2, fmaf(pa0[ni].x, CPM, fmaf(pb0[ni].x, CPO, log2p_small(fmaf(pc0[ni].x, 0.1f, 1e-8f)))));
            float s1 = fmaf(accs[ni][1], SC2, fmaf(pa0[ni].y, CPM, fmaf(pb0[ni].y, CPO, log2p_small(fmaf(pc0[ni].y, 0.1f, 1e-8f)))));
            float s2 = fmaf(accs[ni][2], SC2, fmaf(pa1[ni].x, CPM, fmaf(pb1[ni].x, CPO, log2p_small(fmaf(pc1[ni].x, 0.1f, 1e-8f)))));
            float s3 = fmaf(accs[ni][3], SC2, fmaf(pa1[ni].y, CPM, fmaf(pb1[ni].y, CPO, log2p_small(fmaf(pc1[ni].y, 0.1f, 1e-8f)))));
            if (diag) {
                if (cl     > row0) s0 = -1e30f;
                if (cl + 1 > row0) s1 = -1e30f;
                if (cl     > row1) s2 = -1e30f;
                if (cl + 1 > row1) s3 = -1e30f;
            }
            accs[ni][0] = s0; accs[ni][1] = s1; accs[ni][2] = s2; accs[ni][3] = s3;
            ml0 = fmaxf(ml0, fmaxf(s0, s1));
            ml1 = fmaxf(ml1, fmaxf(s2, s3));
        }
#pragma unroll
        for (int o = 1; o < 4; o <<= 1) {
            ml0 = fmaxf(ml0, __shfl_xor_sync(0xffffffffu, ml0, o));
            ml1 = fmaxf(ml1, __shfl_xor_sync(0xffffffffu, ml1, o));
        }
        if (tig == 0) {
            smf[ORDM + wni * 64 + row0] = ml0;
            smf[ORDM + wni * 64 + row1] = ml1;
        }
        float mold0 = smf[ORM + row0];
        float mold1 = smf[ORM + row1];
        __syncthreads();   // #2: redm ready

        float mn0 = fmaxf(fmaxf(mold0, fmaxf(smf[ORDM + row0], smf[ORDM + 64 + row0])),
                          fmaxf(smf[ORDM + 128 + row0], smf[ORDM + 192 + row0]));
        float mn1 = fmaxf(fmaxf(mold1, fmaxf(smf[ORDM + row1], smf[ORDM + 64 + row1])),
                          fmaxf(smf[ORDM + 128 + row1], smf[ORDM + 192 + row1]));
        float al0 = exp2c(mold0 - mn0);
        float al1 = exp2c(mold1 - mn1);

        float sum0 = 0.f, sum1 = 0.f;
#pragma unroll
        for (int ni = 0; ni < 2; ++ni) {
            const int cl = wn + ni * 8 + 2 * tig;
            float p0 = exp2c(accs[ni][0] - mn0);
            float p1 = exp2c(accs[ni][1] - mn0);
            float p2 = exp2c(accs[ni][2] - mn1);
            float p3 = exp2c(accs[ni][3] - mn1);
            sum0 += p0 + p1;
            sum1 += p2 + p3;
            smf[OPS + row0 * FPADP + cl]     = to_tf32(p0);
            smf[OPS + row0 * FPADP + cl + 1] = to_tf32(p1);
            smf[OPS + row1 * FPADP + cl]     = to_tf32(p2);
            smf[OPS + row1 * FPADP + cl + 1] = to_tf32(p3);
        }
#pragma unroll
        for (int o = 1; o < 4; o <<= 1) {
            sum0 += __shfl_xor_sync(0xffffffffu, sum0, o);
            sum1 += __shfl_xor_sync(0xffffffffu, sum1, o);
        }
        if (tig == 0) {
            smf[ORDS + wni * 64 + row0] = sum0;
            smf[ORDS + wni * 64 + row1] = sum1;
        }
#pragma unroll
        for (int ni = 0; ni < 4; ++ni) {
            acc_o[ni][0] *= al0; acc_o[ni][1] *= al0;
            acc_o[ni][2] *= al1; acc_o[ni][3] *= al1;
        }
        __syncthreads();   // #3: Ps + reds ready

        if (t < 64) {
            float mo = smf[ORM + t];
            float mn = fmaxf(fmaxf(mo, fmaxf(smf[ORDM + t], smf[ORDM + 64 + t])),
                             fmaxf(smf[ORDM + 128 + t], smf[ORDM + 192 + t]));
            float a  = exp2c(mo - mn);
            smf[ORL + t] = smf[ORL + t] * a
                         + smf[ORDS + t] + smf[ORDS + 64 + t]
                         + smf[ORDS + 128 + t] + smf[ORDS + 192 + t];
            smf[ORM + t] = mn;
        }

        const float* Pu = smf + OPS;
        const float* Vu = Vb;
#pragma unroll
        for (int ks = 0; ks < 8; ++ks) {
            const int kk = ks * 8 + 2 * tig;
            uint32_t a[4], b[4][2];
            uint2 p0 = *(const uint2*)&Pu[row0 * FPADP + kk];
            uint2 p1 = *(const uint2*)&Pu[row1 * FPADP + kk];
            a[0] = p0.x; a[2] = p0.y; a[1] = p1.x; a[3] = p1.y;
#pragma unroll
            for (int ni = 0; ni < 4; ++ni) {
                const int c = wd + ni * 8 + gid;
                b[ni][0] = *(const uint32_t*)&Vu[kk * FPADV + c];
                b[ni][1] = *(const uint32_t*)&Vu[(kk + 1) * FPADV + c];
            }
#pragma unroll
            for (int ni = 0; ni < 4; ++ni)
                mma16n8k8(acc_o[ni], a, b[ni]);
        }
    }

    __syncthreads();
    const float l0 = 1.f / smf[ORL + row0];
    const float l1 = 1.f / smf[ORL + row1];
    const int bb = bh >> 4;
    const int h  = bh & 15;
    float* o0 = attn + ((size_t)(bb * SEQ + grow0)) * HIDDEN + h * HEAD_DIM;
    float* o1 = attn + ((size_t)(bb * SEQ + grow1)) * HIDDEN + h * HEAD_DIM;
#pragma unroll
    for (int ni = 0; ni < 4; ++ni) {
        const int d = wd + ni * 8 + 2 * tig;
        float2 w0 = {to_tf32(acc_o[ni][0] * l0), to_tf32(acc_o[ni][1] * l0)};
        float2 w1 = {to_tf32(acc_o[ni][2] * l1), to_tf32(acc_o[ni][3] * l1)};
        *(float2*)(o0 + d) = w0;
        *(float2*)(o1 + d) = w1;
    }
}

// ============================================================================
// host launcher
// ============================================================================
extern "C" void kernel_launch(void* const* d_in, const int* in_sizes, int n_in,
                              void* d_out, int out_size)
{
    const float* x   = (const float*)d_in[0];
    const float* pm  = (const float*)d_in[1];
    const float* pol = (const float*)d_in[2];
    const float* mw  = (const float*)d_in[3];
    const float* Wq  = (const float*)d_in[4];
    const float* Wk  = (const float*)d_in[5];
    const float* Wv  = (const float*)d_in[6];
    const float* Wo  = (const float*)d_in[7];
    const float* bo  = (const float*)d_in[8];
    float* out = (float*)d_out;

    float *gq, *gk, *gv, *ga, *gw, *gx;
    cudaGetSymbolAddress((void**)&gq, g_q);
    cudaGetSymbolAddress((void**)&gk, g_k);
    cudaGetSymbolAddress((void**)&gv, g_v);
    cudaGetSymbolAddress((void**)&ga, g_attn);
    cudaGetSymbolAddress((void**)&gw, g_wt);
    cudaGetSymbolAddress((void**)&gx, g_xc);

    cudaFuncSetAttribute(flash_kernel,
                         cudaFuncAttributeMaxDynamicSharedMemorySize, FLASH_SMEM);
    cudaFuncSetAttribute(gemm_mma_kernel,
                         cudaFuncAttributeMaxDynamicSharedMemorySize, GEMM_SMEM);

    float* wtq = gw;
    float* wtk = gw + (size_t)HIDDEN * HIDDEN;
    float* wtv = gw + 2 * (size_t)HIDDEN * HIDDEN;
    float* wto = gw + 3 * (size_t)HIDDEN * HIDDEN;

    // K0: combined prep (x rounding + 4 weight transposes)
    prep_kernel<<<dim3(64, 64, 5), 256>>>(x, Wq, Wk, Wv, Wo, gx, gw);

    // K1: QKV projections (R9 GEMM)
    gemm_mma_kernel<<<dim3(HIDDEN / BN, MROWS / BM, 3), 128, GEMM_SMEM>>>(
        gx, wtq, wtk, wtv, gq, gk, gv, nullptr, 1);

    // K2: RoPE (float2-vectorized) + tf32 rounding of k, v
    int rope_n = BATCH * HEADS * SEQ * 32;
    rope_kernel<<<(rope_n + 255) / 256, 256>>>(gq, gk, gv);

    // K3: tensor-core flash attention (R9 version)
    dim3 gfl(SEQ / 64, BATCH * HEADS);
    flash_kernel<<<gfl, 512, FLASH_SMEM>>>(gq, gk, gv, pm, pol, mw, ga);

    // K4: output projection + bias
    gemm_mma_kernel<<<dim3(HIDDEN / BN, MROWS / BM, 1), 128, GEMM_SMEM>>>(
        ga, wto, wto, wto, out, out, out, bo, 0);
}